// round 4
// baseline (speedup 1.0000x reference)
#include <cuda_runtime.h>
#include <cstdint>

typedef unsigned long long ull;

// ---------- packed f32x2 helpers (Blackwell FFMA2 path) ----------
__device__ __forceinline__ ull pack2_dup(float x) {
    ull r; asm("mov.b64 %0, {%1, %1};" : "=l"(r) : "f"(x)); return r;
}
__device__ __forceinline__ ull ffma2(ull a, ull b, ull c) {
    ull d; asm("fma.rn.f32x2 %0, %1, %2, %3;" : "=l"(d) : "l"(a), "l"(b), "l"(c)); return d;
}
__device__ __forceinline__ ull add2(ull a, ull b) {
    ull d; asm("add.rn.f32x2 %0, %1, %2;" : "=l"(d) : "l"(a), "l"(b)); return d;
}
__device__ __forceinline__ float2 unpack2(ull v) {
    float x, y; asm("mov.b64 {%0, %1}, %2;" : "=f"(x), "=f"(y) : "l"(v));
    float2 f; f.x = x; f.y = y; return f;
}
__device__ __forceinline__ uint32_t smem_u32(const void* p) {
    uint32_t a;
    asm("{ .reg .u64 t; cvta.to.shared.u64 t, %1; cvt.u32.u64 %0, t; }" : "=r"(a) : "l"(p));
    return a;
}
__device__ __forceinline__ uint32_t mapa_rank(uint32_t addr, int r) {
    uint32_t d; asm("mapa.shared::cluster.u32 %0, %1, %2;" : "=r"(d) : "r"(addr), "r"(r));
    return d;
}
__device__ __forceinline__ void st_cluster_f32(uint32_t addr, float v) {
    asm volatile("st.shared::cluster.f32 [%0], %1;" :: "r"(addr), "f"(v) : "memory");
}
__device__ __forceinline__ void cluster_arrive_() {
    asm volatile("barrier.cluster.arrive.aligned;" ::: "memory");
}
__device__ __forceinline__ void cluster_wait_() {
    asm volatile("barrier.cluster.wait.aligned;" ::: "memory");
}

#define S_LEN 2048
#define B_SZ  64
#define D_SZ  512
#define H_SZ  512
#define M_TOT (B_SZ * S_LEN)   // 131072

// ---------- static device scratch ----------
__device__ float g_proj[(size_t)M_TOT * H_SZ];   // 268 MB
__device__ float g_pin [(size_t)M_TOT * H_SZ];   // 268 MB, layout [s][b][g]

// =====================================================================
// GEMM: C[m,n] = act( sum_k A[m,k] * W[n,k] + bias[n] )
//   MODE 0: A = Ain (X), tanh, write g_proj[m*512+n]
//   MODE 1: A = g_proj,  no act, write g_pin[s*32768 + b*512 + n]
// 128x128x16 tiles, 256 threads, 8x8 micro, double-buffered smem,
// A stored pre-duplicated as f32x2 pairs (no per-kk MOV packing).
// =====================================================================
template<int MODE>
__global__ void __launch_bounds__(256, 2)
gemm_kernel(const float* __restrict__ Ain, const float* __restrict__ W,
            const float* __restrict__ bias, int ldw)
{
    __shared__ ull   As2[2][16][128];   // 32 KB (duplicated f32x2 per element)
    __shared__ float Bs [2][16][128];   // 16 KB

    const float* A = (MODE == 0) ? Ain : g_proj;

    const int t  = threadIdx.x;
    const int n0 = blockIdx.x * 128;
    const int m0 = blockIdx.y * 128;
    const int tx = t & 15;        // n micro
    const int ty = t >> 4;        // m micro
    const int lrow = t >> 2;      // 0..63
    const int lc4  = (t & 3) * 4; // 0,4,8,12

    ull acc[8][4];
    #pragma unroll
    for (int i = 0; i < 8; i++)
        #pragma unroll
        for (int j = 0; j < 4; j++) acc[i][j] = 0ull;

    float4 av0, av1, bv0, bv1;

#define G_LOAD(K0)                                                              \
    av0 = *(const float4*)&A[(size_t)(m0 + lrow)      * D_SZ + (K0) + lc4];     \
    av1 = *(const float4*)&A[(size_t)(m0 + lrow + 64) * D_SZ + (K0) + lc4];     \
    bv0 = *(const float4*)&W[(size_t)(n0 + lrow)      * ldw + (K0) + lc4];      \
    bv1 = *(const float4*)&W[(size_t)(n0 + lrow + 64) * ldw + (K0) + lc4];

#define S_STORE(BUF)                                                            \
    As2[BUF][lc4 + 0][lrow] = pack2_dup(av0.x);                                 \
    As2[BUF][lc4 + 1][lrow] = pack2_dup(av0.y);                                 \
    As2[BUF][lc4 + 2][lrow] = pack2_dup(av0.z);                                 \
    As2[BUF][lc4 + 3][lrow] = pack2_dup(av0.w);                                 \
    As2[BUF][lc4 + 0][lrow + 64] = pack2_dup(av1.x);                            \
    As2[BUF][lc4 + 1][lrow + 64] = pack2_dup(av1.y);                            \
    As2[BUF][lc4 + 2][lrow + 64] = pack2_dup(av1.z);                            \
    As2[BUF][lc4 + 3][lrow + 64] = pack2_dup(av1.w);                            \
    Bs[BUF][lc4 + 0][lrow] = bv0.x; Bs[BUF][lc4 + 1][lrow] = bv0.y;             \
    Bs[BUF][lc4 + 2][lrow] = bv0.z; Bs[BUF][lc4 + 3][lrow] = bv0.w;             \
    Bs[BUF][lc4 + 0][lrow + 64] = bv1.x; Bs[BUF][lc4 + 1][lrow + 64] = bv1.y;   \
    Bs[BUF][lc4 + 2][lrow + 64] = bv1.z; Bs[BUF][lc4 + 3][lrow + 64] = bv1.w;

    G_LOAD(0);
    S_STORE(0);
    __syncthreads();

    for (int tile = 0; tile < 32; tile++) {
        const int cur = tile & 1;
        if (tile + 1 < 32) { G_LOAD((tile + 1) * 16); }

        #pragma unroll
        for (int kk = 0; kk < 16; kk++) {
            ulonglong2 b01 = *(const ulonglong2*)&Bs[cur][kk][tx * 8];
            ulonglong2 b23 = *(const ulonglong2*)&Bs[cur][kk][tx * 8 + 4];
            ulonglong2 ad0 = *(const ulonglong2*)&As2[cur][kk][ty * 8];
            ulonglong2 ad1 = *(const ulonglong2*)&As2[cur][kk][ty * 8 + 2];
            ulonglong2 ad2 = *(const ulonglong2*)&As2[cur][kk][ty * 8 + 4];
            ulonglong2 ad3 = *(const ulonglong2*)&As2[cur][kk][ty * 8 + 6];
            ull ap[8] = {ad0.x, ad0.y, ad1.x, ad1.y, ad2.x, ad2.y, ad3.x, ad3.y};
            #pragma unroll
            for (int i = 0; i < 8; i++) {
                acc[i][0] = ffma2(ap[i], b01.x, acc[i][0]);
                acc[i][1] = ffma2(ap[i], b01.y, acc[i][1]);
                acc[i][2] = ffma2(ap[i], b23.x, acc[i][2]);
                acc[i][3] = ffma2(ap[i], b23.y, acc[i][3]);
            }
        }

        if (tile + 1 < 32) {
            S_STORE((tile + 1) & 1);
            __syncthreads();
        }
    }
#undef G_LOAD
#undef S_STORE

    float bvals[8];
    #pragma unroll
    for (int j = 0; j < 8; j++) bvals[j] = bias[n0 + tx * 8 + j];

    #pragma unroll
    for (int i = 0; i < 8; i++) {
        const int m = m0 + ty * 8 + i;
        float v[8];
        #pragma unroll
        for (int jp = 0; jp < 4; jp++) {
            float2 p = unpack2(acc[i][jp]);
            v[2 * jp + 0] = p.x + bvals[2 * jp + 0];
            v[2 * jp + 1] = p.y + bvals[2 * jp + 1];
        }
        if (MODE == 0) {
            #pragma unroll
            for (int j = 0; j < 8; j++) v[j] = tanhf(v[j]);
            float* dst = &g_proj[(size_t)m * H_SZ + n0 + tx * 8];
            *(float4*)(dst + 0) = make_float4(v[0], v[1], v[2], v[3]);
            *(float4*)(dst + 4) = make_float4(v[4], v[5], v[6], v[7]);
        } else {
            const int ss = m & (S_LEN - 1);
            const int bb = m >> 11;
            float* dst = &g_pin[(size_t)ss * (B_SZ * H_SZ) + (size_t)bb * H_SZ + n0 + tx * 8];
            *(float4*)(dst + 0) = make_float4(v[0], v[1], v[2], v[3]);
            *(float4*)(dst + 4) = make_float4(v[4], v[5], v[6], v[7]);
        }
    }
}

// =====================================================================
// Scan: 2048 sequential steps  h = tanh(pin[s] + h @ Wr2^T)
// Grid: 128 CTAs = 16 clusters of 8. Cluster = one batch-group (4 batches),
// rank = col-group (64 cols). Wr2 slice register-resident (64 f/thread).
// h exchanged via DSMEM broadcast (st.shared::cluster) + split cluster
// barrier (arrive after broadcasts, DRAM out-store in the window, then wait).
// =====================================================================
__global__ void __launch_bounds__(512, 1) __cluster_dims__(8, 1, 1)
scan_kernel(const float* __restrict__ Wr, float* __restrict__ out)
{
    __shared__ float h_s[2][H_SZ * 4];   // double-buffered [k][b], 16 KB
    __shared__ float red[8 * 64 * 4];    // [oct][c][b], 8 KB

    const int t   = threadIdx.x;
    const int q   = blockIdx.x & 7;      // cluster rank == col group (64 cols)
    const int g   = blockIdx.x >> 3;     // batch group (4 batches)
    const int c   = t & 63;              // col within group
    const int oct = t >> 6;              // k-octant (64 k each)

    // ---- register-resident Wr2 slice: row (q*64+c), k in [oct*64, oct*64+64) ----
    const float* wrow = Wr + (size_t)(q * 64 + c) * 1024 + 512 + oct * 64;
    float w[64];
    #pragma unroll
    for (int i = 0; i < 16; i++) {
        float4 v = *(const float4*)&wrow[i * 4];
        w[4 * i + 0] = v.x; w[4 * i + 1] = v.y; w[4 * i + 2] = v.z; w[4 * i + 3] = v.w;
    }

    // reduce-phase identity (threads 0..255 own one (col, batch) output)
    const int  cb      = t & 63;
    const int  bb      = (t >> 6) & 3;
    const bool red_thr = (t < 256);
    const int  b_glob  = g * 4 + bb;

    // DSMEM addresses of this thread's h slot in all 8 ranks (buffer 0)
    uint32_t my_slot = smem_u32(&h_s[0][(q * 64 + cb) * 4 + bb]);
    uint32_t raddr[8];
    #pragma unroll
    for (int r = 0; r < 8; r++) raddr[r] = mapa_rank(my_slot, r);

    const size_t pin_off = (size_t)b_glob * H_SZ + q * 64 + cb;
    const size_t out_off = (size_t)b_glob * ((size_t)S_LEN * H_SZ) + q * 64 + cb;
    const uint32_t BUF_BYTES = (uint32_t)(H_SZ * 4 * sizeof(float));

    // ---------------- step 0 (h == 0): val = tanh(pin[0]) ----------------
    {
        float p0 = __ldg(&g_pin[pin_off]);
        if (red_thr) {
            const float val = tanhf(p0);
            #pragma unroll
            for (int r = 0; r < 8; r++) st_cluster_f32(raddr[r] + BUF_BYTES, val); // buf 1
            cluster_arrive_();
            out[out_off] = val;
        } else {
            cluster_arrive_();
        }
        cluster_wait_();
    }

    float p_cur = __ldg(&g_pin[(size_t)1 * (B_SZ * H_SZ) + pin_off]);

    // ---------------- steps 1 .. 2047 ----------------
    for (int s = 1; s < S_LEN; s++) {
        // octant dot: k in [oct*64, oct*64+64), 4 batches via 2 packed accs,
        // 4 independent FFMA2 chains to cover latency.
        const float* hb = &h_s[s & 1][oct * 256];
        ull a0 = 0ull, a1 = 0ull, a2 = 0ull, a3 = 0ull;
        #pragma unroll
        for (int kk = 0; kk < 64; kk += 2) {
            ulonglong2 hv0 = *(const ulonglong2*)&hb[kk * 4];
            ulonglong2 hv1 = *(const ulonglong2*)&hb[kk * 4 + 4];
            ull wp0 = pack2_dup(w[kk]);
            ull wp1 = pack2_dup(w[kk + 1]);
            a0 = ffma2(hv0.x, wp0, a0);
            a1 = ffma2(hv0.y, wp0, a1);
            a2 = ffma2(hv1.x, wp1, a2);
            a3 = ffma2(hv1.y, wp1, a3);
        }
        *(ull*)&red[oct * 256 + c * 4 + 0] = add2(a0, a2);
        *(ull*)&red[oct * 256 + c * 4 + 2] = add2(a1, a3);
        __syncthreads();

        float p_next = 0.0f;
        if (s + 1 < S_LEN)
            p_next = __ldg(&g_pin[(size_t)(s + 1) * (B_SZ * H_SZ) + pin_off]);

        float val = 0.0f;
        if (red_thr) {
            float sum = p_cur +
                red[0 * 256 + cb * 4 + bb] + red[1 * 256 + cb * 4 + bb] +
                red[2 * 256 + cb * 4 + bb] + red[3 * 256 + cb * 4 + bb] +
                red[4 * 256 + cb * 4 + bb] + red[5 * 256 + cb * 4 + bb] +
                red[6 * 256 + cb * 4 + bb] + red[7 * 256 + cb * 4 + bb];
            val = tanhf(sum);

            // broadcast new h into NEXT buffer of every cluster CTA (release by arrive)
            const uint32_t boff = ((s + 1) & 1) ? BUF_BYTES : 0u;
            #pragma unroll
            for (int r = 0; r < 8; r++) st_cluster_f32(raddr[r] + boff, val);
        }
        cluster_arrive_();

        // in the arrive->wait window: fire-and-forget DRAM output store
        if (red_thr) out[out_off + (size_t)s * H_SZ] = val;

        cluster_wait_();
        p_cur = p_next;
    }
}

// =====================================================================
extern "C" void kernel_launch(void* const* d_in, const int* in_sizes, int n_in,
                              void* d_out, int out_size)
{
    const float* X  = (const float*)d_in[0];
    const float* Wp = (const float*)d_in[1];
    const float* bp = (const float*)d_in[2];
    const float* Wr = (const float*)d_in[3];
    const float* br = (const float*)d_in[4];
    float* out = (float*)d_out;

    gemm_kernel<0><<<dim3(4, 1024), 256>>>(X, Wp, bp, 512);
    gemm_kernel<1><<<dim3(4, 1024), 256>>>(nullptr, Wr, br, 1024);
    scan_kernel<<<128, 512>>>(Wr, out);
}